// round 13
// baseline (speedup 1.0000x reference)
#include <cuda_runtime.h>
#include <math.h>
#include <stdint.h>

// Problem constants
#define B_SZ   2
#define T_SEQ  2048
#define E_DIM  2048
#define NH     16
#define NKV    8
#define HD     128
#define ROWS   (B_SZ * T_SEQ)        // 4096
#define QW     (NH * HD)             // 2048
#define KW     (NKV * HD)            // 1024

// Scratch (static device globals; no dynamic allocation allowed)
__device__ float g_Q[(size_t)ROWS * QW];     // 32 MB
__device__ float g_K[(size_t)ROWS * KW];     // 16 MB
__device__ float g_V[(size_t)ROWS * KW];     // 16 MB
__device__ float g_AO[(size_t)ROWS * QW];    // 32 MB
__device__ float g_WT[(size_t)E_DIM * E_DIM];// 16 MB (transposed tf32 weight, reused)
__device__ float g_cos[T_SEQ * (HD / 2)];
__device__ float g_sin[T_SEQ * (HD / 2)];

// ---------------------------------------------------------------------------
// Helpers
// ---------------------------------------------------------------------------
__device__ __forceinline__ float to_tf32(float x) {
    uint32_t u;
    asm("cvt.rna.tf32.f32 %0, %1;" : "=r"(u) : "f"(x));
    return __uint_as_float(u);
}

__device__ __forceinline__ void mma_tf32(float* d, const uint32_t* a, const uint32_t* b) {
    asm volatile(
        "mma.sync.aligned.m16n8k8.row.col.f32.tf32.tf32.f32 "
        "{%0,%1,%2,%3}, {%4,%5,%6,%7}, {%8,%9}, {%0,%1,%2,%3};\n"
        : "+f"(d[0]), "+f"(d[1]), "+f"(d[2]), "+f"(d[3])
        : "r"(a[0]), "r"(a[1]), "r"(a[2]), "r"(a[3]), "r"(b[0]), "r"(b[1]));
}

// ---------------------------------------------------------------------------
// TF32 mma.sync GEMM: C[M,N] = A[M,K] @ Bt[N,K]^T  (both K-major).
// A raw fp32 (rna-tf32 at staging); Bt pre-rounded to tf32.
// CTA 128x128, BK=32, 256 threads = 8 warps (2m x 4n), warp tile 64x32.
// Fragment-major ("quad") smem: each A fragment = 1 LDS.128; each B LDS.128
// feeds 2 n-tile fragments. Swizzle slot = lq*4 + (j ^ k8): conflict-free
// for both STS.128 staging and LDS.128 consumption.
// Requires M%128==0, N%128==0, K%32==0.
// ---------------------------------------------------------------------------
#define GBK 32
#define STG_BYTES 32768          // 16KB A + 16KB B per stage
#define GEMM_SMEM (2 * STG_BYTES)

__global__ __launch_bounds__(256) void gemm_mma(
    const float* __restrict__ A, const float* __restrict__ Bt,
    float* __restrict__ C, int M, int N, int K)
{
    extern __shared__ char smc[];
    const int tid = threadIdx.x;
    const int lane = tid & 31, warp = tid >> 5;
    const int lq = lane >> 2, s4 = lane & 3;
    const int wm = warp >> 2, wn = warp & 3;      // warp grid 2(m) x 4(n)
    const int m0 = blockIdx.y * 128, n0 = blockIdx.x * 128;

    // Staging role: thread -> (k8-chunk, 16-row group, row-in-group)
    const int sk8 = tid & 3;          // which k8 block (cols sk8*8..+7)
    const int slq = (tid >> 2) & 7;   // row lq within group
    const int sgrp = tid >> 5;        // 16-row group 0..7

    const float* Ag0 = A + (size_t)(m0 + sgrp * 16 + slq) * K + sk8 * 8;
    const float* Ag1 = Ag0 + (size_t)8 * K;
    const float* Bg0 = Bt + (size_t)(n0 + sgrp * 16 + slq) * K + sk8 * 8;
    const float* Bg1 = Bg0 + (size_t)8 * K;

    const int sts_base = (sk8 * 8 + sgrp) * 32;   // float4 index base

    float ar0[8], ar1[8], br0[8], br1[8];

    auto LDGALL = [&](int kt) {
        const float* a0 = Ag0 + kt * GBK;
        const float* a1 = Ag1 + kt * GBK;
        const float* b0 = Bg0 + kt * GBK;
        const float* b1 = Bg1 + kt * GBK;
        *(float4*)(ar0)     = *(const float4*)(a0);
        *(float4*)(ar0 + 4) = *(const float4*)(a0 + 4);
        *(float4*)(ar1)     = *(const float4*)(a1);
        *(float4*)(ar1 + 4) = *(const float4*)(a1 + 4);
        *(float4*)(br0)     = *(const float4*)(b0);
        *(float4*)(br0 + 4) = *(const float4*)(b0 + 4);
        *(float4*)(br1)     = *(const float4*)(b1);
        *(float4*)(br1 + 4) = *(const float4*)(b1 + 4);
    };
    auto STSALL = [&](int st) {
        float4* As = (float4*)(smc + st * STG_BYTES);
        float4* Bs = (float4*)(smc + st * STG_BYTES + 16384);
#pragma unroll
        for (int j = 0; j < 4; j++) {
            const int slot = slq * 4 + (j ^ sk8);
            As[sts_base + slot] = make_float4(to_tf32(ar0[j]), to_tf32(ar1[j]),
                                              to_tf32(ar0[j + 4]), to_tf32(ar1[j + 4]));
            Bs[sts_base + slot] = make_float4(br0[j], br1[j], br0[j + 4], br1[j + 4]);
        }
    };

    float acc[4][4][4];
#pragma unroll
    for (int mi = 0; mi < 4; mi++)
#pragma unroll
        for (int ni = 0; ni < 4; ni++)
#pragma unroll
            for (int j = 0; j < 4; j++) acc[mi][ni][j] = 0.f;

    const int nk = K / GBK;

    LDGALL(0);
    STSALL(0);
    __syncthreads();

    for (int kt = 0; kt < nk; kt++) {
        if (kt + 1 < nk) LDGALL(kt + 1);

        const float4* As = (const float4*)(smc + (kt & 1) * STG_BYTES);
        const float4* Bs = (const float4*)(smc + (kt & 1) * STG_BYTES + 16384);

#pragma unroll
        for (int k8 = 0; k8 < 4; k8++) {
            const int cslot = lq * 4 + (s4 ^ k8);
            uint32_t af[4][4], bf[4][2];
#pragma unroll
            for (int mi = 0; mi < 4; mi++) {
                float4 q = As[(k8 * 8 + wm * 4 + mi) * 32 + cslot];
                af[mi][0] = __float_as_uint(q.x); af[mi][1] = __float_as_uint(q.y);
                af[mi][2] = __float_as_uint(q.z); af[mi][3] = __float_as_uint(q.w);
            }
#pragma unroll
            for (int g = 0; g < 2; g++) {
                float4 q = Bs[(k8 * 8 + wn * 2 + g) * 32 + cslot];
                bf[g * 2 + 0][0] = __float_as_uint(q.x); bf[g * 2 + 0][1] = __float_as_uint(q.z);
                bf[g * 2 + 1][0] = __float_as_uint(q.y); bf[g * 2 + 1][1] = __float_as_uint(q.w);
            }
#pragma unroll
            for (int mi = 0; mi < 4; mi++)
#pragma unroll
                for (int ni = 0; ni < 4; ni++)
                    mma_tf32(acc[mi][ni], af[mi], bf[ni]);
        }

        if (kt + 1 < nk) {
            STSALL((kt + 1) & 1);
            __syncthreads();
        }
    }

    // Epilogue: c0,c1 = (row g, col t*2, t*2+1); c2,c3 = (row g+8, same cols)
#pragma unroll
    for (int mi = 0; mi < 4; mi++) {
        const int r0 = m0 + wm * 64 + mi * 16 + lq;
#pragma unroll
        for (int ni = 0; ni < 4; ni++) {
            const int c = n0 + wn * 32 + ni * 8 + s4 * 2;
            *(float2*)(C + (size_t)r0 * N + c)       = make_float2(acc[mi][ni][0], acc[mi][ni][1]);
            *(float2*)(C + (size_t)(r0 + 8) * N + c) = make_float2(acc[mi][ni][2], acc[mi][ni][3]);
        }
    }
}

// ---------------------------------------------------------------------------
// Transpose + tf32 rounding: out[C][R] = rna_tf32(in[R][C])^T
// Block (32,8), grid (C/32, R/32).
// ---------------------------------------------------------------------------
__global__ void transpose_round_kernel(const float* __restrict__ in, float* __restrict__ out,
                                       int R, int C)
{
    __shared__ float t[32][33];
    const int bx = blockIdx.x * 32, by = blockIdx.y * 32;
    const int tx = threadIdx.x, ty = threadIdx.y;
#pragma unroll
    for (int i = 0; i < 32; i += 8)
        t[ty + i][tx] = to_tf32(in[(size_t)(by + ty + i) * C + bx + tx]);
    __syncthreads();
#pragma unroll
    for (int i = 0; i < 32; i += 8)
        out[(size_t)(bx + ty + i) * R + by + tx] = t[tx][ty + i];
}

// ---------------------------------------------------------------------------
// RoPE table: cos/sin in double precision
// ---------------------------------------------------------------------------
__global__ void rope_table_kernel()
{
    int idx = blockIdx.x * blockDim.x + threadIdx.x;
    if (idx >= T_SEQ * (HD / 2)) return;
    int t = idx / (HD / 2);
    int i = idx % (HD / 2);
    double inv = pow(10000.0, -(double)(2 * i) / (double)HD);
    double ang = (double)t * inv;
    double s, c;
    sincos(ang, &s, &c);
    g_cos[idx] = (float)c;
    g_sin[idx] = (float)s;
}

// Apply RoPE in-place to tensor with layout (B*T, nheads*128)
__global__ void rope_apply_kernel(float* __restrict__ x, int nheads)
{
    int idx = blockIdx.x * blockDim.x + threadIdx.x;
    int pairs_per_row = nheads * (HD / 2);
    if (idx >= ROWS * pairs_per_row) return;
    int row = idx / pairs_per_row;
    int p = idx - row * pairs_per_row;
    int h = p / (HD / 2);
    int i = p - h * (HD / 2);
    int t = row & (T_SEQ - 1);
    float c = g_cos[t * (HD / 2) + i];
    float s = g_sin[t * (HD / 2) + i];
    float* base = x + (size_t)row * nheads * HD + h * HD + 2 * i;
    float x0 = base[0], x1 = base[1];
    base[0] = x0 * c - x1 * s;
    base[1] = x0 * s + x1 * c;
}

// ---------------------------------------------------------------------------
// Flash attention, fp32, causal, GQA (2 q heads per kv head). (unchanged)
// ---------------------------------------------------------------------------
__global__ __launch_bounds__(256) void attn_kernel()
{
    __shared__ float Ks[32 * 128];
    __shared__ float Vs[32 * 128];

    const int tid = threadIdx.x;
    const int w = tid >> 5, lane = tid & 31;
    const int rl = (w << 2) + (lane >> 3);   // local q row 0..31
    const int g = lane & 7;                  // 16-dim group 0..7

    const int qb = blockIdx.x;               // q tile index
    const int bh = blockIdx.y;
    const int b = bh >> 4, h = bh & 15;
    const int kh = h >> 1;                   // GQA: kv head
    const int qi = qb * 32 + rl;

    const float scale = 0.08838834764831845f;  // 128^-0.5

    float q[16], o[16];
    const float* qptr = g_Q + (size_t)(b * T_SEQ + qi) * QW + h * HD + g * 16;
#pragma unroll
    for (int j = 0; j < 16; j++) { q[j] = qptr[j] * scale; o[j] = 0.f; }

    float m = -INFINITY, l = 0.f;

    for (int t0 = 0; t0 <= qb; t0++) {
        const int k0 = t0 * 32;
        const float* Kb = g_K + (size_t)(b * T_SEQ + k0) * KW + kh * HD;
        const float* Vb = g_V + (size_t)(b * T_SEQ + k0) * KW + kh * HD;

        __syncthreads();
#pragma unroll
        for (int it = 0; it < 4; it++) {
            int idx = tid + it * 256;        // float4 index 0..1023
            int r = idx >> 5;
            int c = idx & 31;
            ((float4*)Ks)[idx] = *(const float4*)(Kb + (size_t)r * KW + c * 4);
            ((float4*)Vs)[idx] = *(const float4*)(Vb + (size_t)r * KW + c * 4);
        }
        __syncthreads();

        const bool diag = (t0 == qb);
        float sreg[4];
        float tmax = -INFINITY;

#pragma unroll
        for (int kk = 0; kk < 32; kk++) {
            const float4* kr = (const float4*)(Ks + kk * 128 + g * 16);
            float4 ka = kr[0], kb2 = kr[1], kc = kr[2], kd = kr[3];
            float s;
            s = q[0] * ka.x;
            s = fmaf(q[1],  ka.y,  s); s = fmaf(q[2],  ka.z,  s); s = fmaf(q[3],  ka.w,  s);
            s = fmaf(q[4],  kb2.x, s); s = fmaf(q[5],  kb2.y, s); s = fmaf(q[6],  kb2.z, s); s = fmaf(q[7],  kb2.w, s);
            s = fmaf(q[8],  kc.x,  s); s = fmaf(q[9],  kc.y,  s); s = fmaf(q[10], kc.z,  s); s = fmaf(q[11], kc.w,  s);
            s = fmaf(q[12], kd.x,  s); s = fmaf(q[13], kd.y,  s); s = fmaf(q[14], kd.z,  s); s = fmaf(q[15], kd.w,  s);
            s += __shfl_xor_sync(0xffffffffu, s, 1);
            s += __shfl_xor_sync(0xffffffffu, s, 2);
            s += __shfl_xor_sync(0xffffffffu, s, 4);
            if (diag && (k0 + kk > qi)) s = -INFINITY;
            if ((kk & 7) == g) sreg[kk >> 3] = s;
            tmax = fmaxf(tmax, s);
        }

        float mnew = fmaxf(m, tmax);
        float corr = __expf(m - mnew);
        l *= corr;
#pragma unroll
        for (int j = 0; j < 16; j++) o[j] *= corr;
        m = mnew;

#pragma unroll
        for (int kk = 0; kk < 32; kk++) {
            float s = __shfl_sync(0xffffffffu, sreg[kk >> 3], kk & 7, 8);
            float p = __expf(s - m);
            l += p;
            const float4* vr = (const float4*)(Vs + kk * 128 + g * 16);
            float4 va = vr[0], vb2 = vr[1], vc = vr[2], vd = vr[3];
            o[0]  = fmaf(p, va.x,  o[0]);  o[1]  = fmaf(p, va.y,  o[1]);
            o[2]  = fmaf(p, va.z,  o[2]);  o[3]  = fmaf(p, va.w,  o[3]);
            o[4]  = fmaf(p, vb2.x, o[4]);  o[5]  = fmaf(p, vb2.y, o[5]);
            o[6]  = fmaf(p, vb2.z, o[6]);  o[7]  = fmaf(p, vb2.w, o[7]);
            o[8]  = fmaf(p, vc.x,  o[8]);  o[9]  = fmaf(p, vc.y,  o[9]);
            o[10] = fmaf(p, vc.z,  o[10]); o[11] = fmaf(p, vc.w,  o[11]);
            o[12] = fmaf(p, vd.x,  o[12]); o[13] = fmaf(p, vd.y,  o[13]);
            o[14] = fmaf(p, vd.z,  o[14]); o[15] = fmaf(p, vd.w,  o[15]);
        }
    }

    const float inv = 1.f / l;
    float* outp = g_AO + (size_t)(b * T_SEQ + qi) * QW + h * HD + g * 16;
#pragma unroll
    for (int v4 = 0; v4 < 4; v4++) {
        float4 ov = make_float4(o[v4 * 4 + 0] * inv, o[v4 * 4 + 1] * inv,
                                o[v4 * 4 + 2] * inv, o[v4 * 4 + 3] * inv);
        *(float4*)(outp + v4 * 4) = ov;
    }
}

// ---------------------------------------------------------------------------
// kernel_launch: x, mask, wq, wk, wv, wo -> out (B,T,E) fp32
// ---------------------------------------------------------------------------
extern "C" void kernel_launch(void* const* d_in, const int* in_sizes, int n_in,
                              void* d_out, int out_size)
{
    const float* x  = (const float*)d_in[0];
    // d_in[1] = causal mask (unused: causality computed directly)
    const float* wq = (const float*)d_in[2];
    const float* wk = (const float*)d_in[3];
    const float* wv = (const float*)d_in[4];
    const float* wo = (const float*)d_in[5];
    float* out = (float*)d_out;

    float *Qp, *Kp, *Vp, *AOp, *WTp;
    cudaGetSymbolAddress((void**)&Qp,  g_Q);
    cudaGetSymbolAddress((void**)&Kp,  g_K);
    cudaGetSymbolAddress((void**)&Vp,  g_V);
    cudaGetSymbolAddress((void**)&AOp, g_AO);
    cudaGetSymbolAddress((void**)&WTp, g_WT);

    cudaFuncSetAttribute(gemm_mma, cudaFuncAttributeMaxDynamicSharedMemorySize, GEMM_SMEM);

    // Q = X @ Wq
    {
        dim3 tg(E_DIM / 32, E_DIM / 32);
        transpose_round_kernel<<<tg, dim3(32, 8)>>>(wq, WTp, E_DIM, QW);
        dim3 grid(QW / 128, ROWS / 128);
        gemm_mma<<<grid, 256, GEMM_SMEM>>>(x, WTp, Qp, ROWS, QW, E_DIM);
    }
    // K = X @ Wk
    {
        dim3 tg(KW / 32, E_DIM / 32);
        transpose_round_kernel<<<tg, dim3(32, 8)>>>(wk, WTp, E_DIM, KW);
        dim3 grid(KW / 128, ROWS / 128);
        gemm_mma<<<grid, 256, GEMM_SMEM>>>(x, WTp, Kp, ROWS, KW, E_DIM);
    }
    // V = X @ Wv
    {
        dim3 tg(KW / 32, E_DIM / 32);
        transpose_round_kernel<<<tg, dim3(32, 8)>>>(wv, WTp, E_DIM, KW);
        dim3 grid(KW / 128, ROWS / 128);
        gemm_mma<<<grid, 256, GEMM_SMEM>>>(x, WTp, Vp, ROWS, KW, E_DIM);
    }

    // RoPE
    {
        int n = T_SEQ * (HD / 2);
        rope_table_kernel<<<(n + 255) / 256, 256>>>();
        int nq = ROWS * NH * (HD / 2);
        rope_apply_kernel<<<(nq + 255) / 256, 256>>>(Qp, NH);
        int nk = ROWS * NKV * (HD / 2);
        rope_apply_kernel<<<(nk + 255) / 256, 256>>>(Kp, NKV);
    }

    // Attention
    {
        dim3 grid(T_SEQ / 32, B_SZ * NH);
        attn_kernel<<<grid, 256>>>();
    }

    // out = AO @ Wo
    {
        dim3 tg(E_DIM / 32, QW / 32);
        transpose_round_kernel<<<tg, dim3(32, 8)>>>(wo, WTp, QW, E_DIM);
        dim3 grid(E_DIM / 128, ROWS / 128);
        gemm_mma<<<grid, 256, GEMM_SMEM>>>(AOp, WTp, out, ROWS, E_DIM, E_DIM);
    }
}

// round 14
// speedup vs baseline: 1.0111x; 1.0111x over previous
#include <cuda_runtime.h>
#include <math.h>
#include <stdint.h>

// Problem constants
#define B_SZ   2
#define T_SEQ  2048
#define E_DIM  2048
#define NH     16
#define NKV    8
#define HD     128
#define ROWS   (B_SZ * T_SEQ)        // 4096
#define QW     (NH * HD)             // 2048
#define KW     (NKV * HD)            // 1024

// Scratch (static device globals; no dynamic allocation allowed)
__device__ float g_Q[(size_t)ROWS * QW];     // 32 MB
__device__ float g_K[(size_t)ROWS * KW];     // 16 MB
__device__ float g_V[(size_t)ROWS * KW];     // 16 MB
__device__ float g_AO[(size_t)ROWS * QW];    // 32 MB
__device__ float g_WT[(size_t)E_DIM * E_DIM];// 16 MB (transposed tf32 weight, reused)
__device__ float g_cos[T_SEQ * (HD / 2)];
__device__ float g_sin[T_SEQ * (HD / 2)];

// ---------------------------------------------------------------------------
// Helpers
// ---------------------------------------------------------------------------
__device__ __forceinline__ float to_tf32(float x) {
    uint32_t u;
    asm("cvt.rna.tf32.f32 %0, %1;" : "=r"(u) : "f"(x));
    return __uint_as_float(u);
}

__device__ __forceinline__ void mma_tf32(float* d, const uint32_t* a, const uint32_t* b) {
    asm volatile(
        "mma.sync.aligned.m16n8k8.row.col.f32.tf32.tf32.f32 "
        "{%0,%1,%2,%3}, {%4,%5,%6,%7}, {%8,%9}, {%0,%1,%2,%3};\n"
        : "+f"(d[0]), "+f"(d[1]), "+f"(d[2]), "+f"(d[3])
        : "r"(a[0]), "r"(a[1]), "r"(a[2]), "r"(a[3]), "r"(b[0]), "r"(b[1]));
}

// ---------------------------------------------------------------------------
// TF32 mma.sync GEMM: C[M,N] = A[M,K] @ Bt[N,K]^T  (both K-major).
// A raw fp32 (rna-tf32 at staging); Bt pre-rounded to tf32.
// CTA 128x128, BK=32, 256 threads = 8 warps (2m x 4n), warp tile 64x32.
// Fragment-major ("quad") smem: each A fragment = 1 LDS.128; each B LDS.128
// feeds 2 n-tile fragments. Swizzle slot = lq*4 + (j ^ k8): conflict-free
// for both STS.128 staging and LDS.128 consumption.
// Requires M%128==0, N%128==0, K%32==0.
// ---------------------------------------------------------------------------
#define GBK 32
#define STG_BYTES 32768          // 16KB A + 16KB B per stage
#define GEMM_SMEM (2 * STG_BYTES)

__global__ __launch_bounds__(256) void gemm_mma(
    const float* __restrict__ A, const float* __restrict__ Bt,
    float* __restrict__ C, int M, int N, int K)
{
    extern __shared__ char smc[];
    const int tid = threadIdx.x;
    const int lane = tid & 31, warp = tid >> 5;
    const int lq = lane >> 2, s4 = lane & 3;
    const int wm = warp >> 2, wn = warp & 3;      // warp grid 2(m) x 4(n)
    const int m0 = blockIdx.y * 128, n0 = blockIdx.x * 128;

    // Staging role: thread -> (k8-chunk, 16-row group, row-in-group)
    const int sk8 = tid & 3;          // which k8 block (cols sk8*8..+7)
    const int slq = (tid >> 2) & 7;   // row lq within group
    const int sgrp = tid >> 5;        // 16-row group 0..7

    const float* Ag0 = A + (size_t)(m0 + sgrp * 16 + slq) * K + sk8 * 8;
    const float* Ag1 = Ag0 + (size_t)8 * K;
    const float* Bg0 = Bt + (size_t)(n0 + sgrp * 16 + slq) * K + sk8 * 8;
    const float* Bg1 = Bg0 + (size_t)8 * K;

    const int sts_base = (sk8 * 8 + sgrp) * 32;   // float4 index base

    float ar0[8], ar1[8], br0[8], br1[8];

    auto LDGALL = [&](int kt) {
        const float* a0 = Ag0 + kt * GBK;
        const float* a1 = Ag1 + kt * GBK;
        const float* b0 = Bg0 + kt * GBK;
        const float* b1 = Bg1 + kt * GBK;
        *(float4*)(ar0)     = *(const float4*)(a0);
        *(float4*)(ar0 + 4) = *(const float4*)(a0 + 4);
        *(float4*)(ar1)     = *(const float4*)(a1);
        *(float4*)(ar1 + 4) = *(const float4*)(a1 + 4);
        *(float4*)(br0)     = *(const float4*)(b0);
        *(float4*)(br0 + 4) = *(const float4*)(b0 + 4);
        *(float4*)(br1)     = *(const float4*)(b1);
        *(float4*)(br1 + 4) = *(const float4*)(b1 + 4);
    };
    auto STSALL = [&](int st) {
        float4* As = (float4*)(smc + st * STG_BYTES);
        float4* Bs = (float4*)(smc + st * STG_BYTES + 16384);
#pragma unroll
        for (int j = 0; j < 4; j++) {
            const int slot = slq * 4 + (j ^ sk8);
            As[sts_base + slot] = make_float4(to_tf32(ar0[j]), to_tf32(ar1[j]),
                                              to_tf32(ar0[j + 4]), to_tf32(ar1[j + 4]));
            Bs[sts_base + slot] = make_float4(br0[j], br1[j], br0[j + 4], br1[j + 4]);
        }
    };

    float acc[4][4][4];
#pragma unroll
    for (int mi = 0; mi < 4; mi++)
#pragma unroll
        for (int ni = 0; ni < 4; ni++)
#pragma unroll
            for (int j = 0; j < 4; j++) acc[mi][ni][j] = 0.f;

    const int nk = K / GBK;

    LDGALL(0);
    STSALL(0);
    __syncthreads();

    for (int kt = 0; kt < nk; kt++) {
        if (kt + 1 < nk) LDGALL(kt + 1);

        const float4* As = (const float4*)(smc + (kt & 1) * STG_BYTES);
        const float4* Bs = (const float4*)(smc + (kt & 1) * STG_BYTES + 16384);

#pragma unroll
        for (int k8 = 0; k8 < 4; k8++) {
            const int cslot = lq * 4 + (s4 ^ k8);
            uint32_t af[4][4], bf[4][2];
#pragma unroll
            for (int mi = 0; mi < 4; mi++) {
                float4 q = As[(k8 * 8 + wm * 4 + mi) * 32 + cslot];
                af[mi][0] = __float_as_uint(q.x); af[mi][1] = __float_as_uint(q.y);
                af[mi][2] = __float_as_uint(q.z); af[mi][3] = __float_as_uint(q.w);
            }
#pragma unroll
            for (int g = 0; g < 2; g++) {
                float4 q = Bs[(k8 * 8 + wn * 2 + g) * 32 + cslot];
                bf[g * 2 + 0][0] = __float_as_uint(q.x); bf[g * 2 + 0][1] = __float_as_uint(q.z);
                bf[g * 2 + 1][0] = __float_as_uint(q.y); bf[g * 2 + 1][1] = __float_as_uint(q.w);
            }
#pragma unroll
            for (int mi = 0; mi < 4; mi++)
#pragma unroll
                for (int ni = 0; ni < 4; ni++)
                    mma_tf32(acc[mi][ni], af[mi], bf[ni]);
        }

        if (kt + 1 < nk) {
            STSALL((kt + 1) & 1);
            __syncthreads();
        }
    }

    // Epilogue: c0,c1 = (row g, col t*2, t*2+1); c2,c3 = (row g+8, same cols)
#pragma unroll
    for (int mi = 0; mi < 4; mi++) {
        const int r0 = m0 + wm * 64 + mi * 16 + lq;
#pragma unroll
        for (int ni = 0; ni < 4; ni++) {
            const int c = n0 + wn * 32 + ni * 8 + s4 * 2;
            *(float2*)(C + (size_t)r0 * N + c)       = make_float2(acc[mi][ni][0], acc[mi][ni][1]);
            *(float2*)(C + (size_t)(r0 + 8) * N + c) = make_float2(acc[mi][ni][2], acc[mi][ni][3]);
        }
    }
}

// ---------------------------------------------------------------------------
// Transpose + tf32 rounding: out[C][R] = rna_tf32(in[R][C])^T
// Block (32,8), grid (C/32, R/32).
// ---------------------------------------------------------------------------
__global__ void transpose_round_kernel(const float* __restrict__ in, float* __restrict__ out,
                                       int R, int C)
{
    __shared__ float t[32][33];
    const int bx = blockIdx.x * 32, by = blockIdx.y * 32;
    const int tx = threadIdx.x, ty = threadIdx.y;
#pragma unroll
    for (int i = 0; i < 32; i += 8)
        t[ty + i][tx] = to_tf32(in[(size_t)(by + ty + i) * C + bx + tx]);
    __syncthreads();
#pragma unroll
    for (int i = 0; i < 32; i += 8)
        out[(size_t)(bx + ty + i) * R + by + tx] = t[tx][ty + i];
}

// ---------------------------------------------------------------------------
// RoPE table: cos/sin in double precision
// ---------------------------------------------------------------------------
__global__ void rope_table_kernel()
{
    int idx = blockIdx.x * blockDim.x + threadIdx.x;
    if (idx >= T_SEQ * (HD / 2)) return;
    int t = idx / (HD / 2);
    int i = idx % (HD / 2);
    double inv = pow(10000.0, -(double)(2 * i) / (double)HD);
    double ang = (double)t * inv;
    double s, c;
    sincos(ang, &s, &c);
    g_cos[idx] = (float)c;
    g_sin[idx] = (float)s;
}

// Apply RoPE in-place to tensor with layout (B*T, nheads*128)
__global__ void rope_apply_kernel(float* __restrict__ x, int nheads)
{
    int idx = blockIdx.x * blockDim.x + threadIdx.x;
    int pairs_per_row = nheads * (HD / 2);
    if (idx >= ROWS * pairs_per_row) return;
    int row = idx / pairs_per_row;
    int p = idx - row * pairs_per_row;
    int h = p / (HD / 2);
    int i = p - h * (HD / 2);
    int t = row & (T_SEQ - 1);
    float c = g_cos[t * (HD / 2) + i];
    float s = g_sin[t * (HD / 2) + i];
    float* base = x + (size_t)row * nheads * HD + h * HD + 2 * i;
    float x0 = base[0], x1 = base[1];
    base[0] = x0 * c - x1 * s;
    base[1] = x0 * s + x1 * c;
}

// ---------------------------------------------------------------------------
// Flash attention, fp32, causal, GQA (2 q heads per kv head). (unchanged)
// ---------------------------------------------------------------------------
__global__ __launch_bounds__(256) void attn_kernel()
{
    __shared__ float Ks[32 * 128];
    __shared__ float Vs[32 * 128];

    const int tid = threadIdx.x;
    const int w = tid >> 5, lane = tid & 31;
    const int rl = (w << 2) + (lane >> 3);   // local q row 0..31
    const int g = lane & 7;                  // 16-dim group 0..7

    const int qb = blockIdx.x;               // q tile index
    const int bh = blockIdx.y;
    const int b = bh >> 4, h = bh & 15;
    const int kh = h >> 1;                   // GQA: kv head
    const int qi = qb * 32 + rl;

    const float scale = 0.08838834764831845f;  // 128^-0.5

    float q[16], o[16];
    const float* qptr = g_Q + (size_t)(b * T_SEQ + qi) * QW + h * HD + g * 16;
#pragma unroll
    for (int j = 0; j < 16; j++) { q[j] = qptr[j] * scale; o[j] = 0.f; }

    float m = -INFINITY, l = 0.f;

    for (int t0 = 0; t0 <= qb; t0++) {
        const int k0 = t0 * 32;
        const float* Kb = g_K + (size_t)(b * T_SEQ + k0) * KW + kh * HD;
        const float* Vb = g_V + (size_t)(b * T_SEQ + k0) * KW + kh * HD;

        __syncthreads();
#pragma unroll
        for (int it = 0; it < 4; it++) {
            int idx = tid + it * 256;        // float4 index 0..1023
            int r = idx >> 5;
            int c = idx & 31;
            ((float4*)Ks)[idx] = *(const float4*)(Kb + (size_t)r * KW + c * 4);
            ((float4*)Vs)[idx] = *(const float4*)(Vb + (size_t)r * KW + c * 4);
        }
        __syncthreads();

        const bool diag = (t0 == qb);
        float sreg[4];
        float tmax = -INFINITY;

#pragma unroll
        for (int kk = 0; kk < 32; kk++) {
            const float4* kr = (const float4*)(Ks + kk * 128 + g * 16);
            float4 ka = kr[0], kb2 = kr[1], kc = kr[2], kd = kr[3];
            float s;
            s = q[0] * ka.x;
            s = fmaf(q[1],  ka.y,  s); s = fmaf(q[2],  ka.z,  s); s = fmaf(q[3],  ka.w,  s);
            s = fmaf(q[4],  kb2.x, s); s = fmaf(q[5],  kb2.y, s); s = fmaf(q[6],  kb2.z, s); s = fmaf(q[7],  kb2.w, s);
            s = fmaf(q[8],  kc.x,  s); s = fmaf(q[9],  kc.y,  s); s = fmaf(q[10], kc.z,  s); s = fmaf(q[11], kc.w,  s);
            s = fmaf(q[12], kd.x,  s); s = fmaf(q[13], kd.y,  s); s = fmaf(q[14], kd.z,  s); s = fmaf(q[15], kd.w,  s);
            s += __shfl_xor_sync(0xffffffffu, s, 1);
            s += __shfl_xor_sync(0xffffffffu, s, 2);
            s += __shfl_xor_sync(0xffffffffu, s, 4);
            if (diag && (k0 + kk > qi)) s = -INFINITY;
            if ((kk & 7) == g) sreg[kk >> 3] = s;
            tmax = fmaxf(tmax, s);
        }

        float mnew = fmaxf(m, tmax);
        float corr = __expf(m - mnew);
        l *= corr;
#pragma unroll
        for (int j = 0; j < 16; j++) o[j] *= corr;
        m = mnew;

#pragma unroll
        for (int kk = 0; kk < 32; kk++) {
            float s = __shfl_sync(0xffffffffu, sreg[kk >> 3], kk & 7, 8);
            float p = __expf(s - m);
            l += p;
            const float4* vr = (const float4*)(Vs + kk * 128 + g * 16);
            float4 va = vr[0], vb2 = vr[1], vc = vr[2], vd = vr[3];
            o[0]  = fmaf(p, va.x,  o[0]);  o[1]  = fmaf(p, va.y,  o[1]);
            o[2]  = fmaf(p, va.z,  o[2]);  o[3]  = fmaf(p, va.w,  o[3]);
            o[4]  = fmaf(p, vb2.x, o[4]);  o[5]  = fmaf(p, vb2.y, o[5]);
            o[6]  = fmaf(p, vb2.z, o[6]);  o[7]  = fmaf(p, vb2.w, o[7]);
            o[8]  = fmaf(p, vc.x,  o[8]);  o[9]  = fmaf(p, vc.y,  o[9]);
            o[10] = fmaf(p, vc.z,  o[10]); o[11] = fmaf(p, vc.w,  o[11]);
            o[12] = fmaf(p, vd.x,  o[12]); o[13] = fmaf(p, vd.y,  o[13]);
            o[14] = fmaf(p, vd.z,  o[14]); o[15] = fmaf(p, vd.w,  o[15]);
        }
    }

    const float inv = 1.f / l;
    float* outp = g_AO + (size_t)(b * T_SEQ + qi) * QW + h * HD + g * 16;
#pragma unroll
    for (int v4 = 0; v4 < 4; v4++) {
        float4 ov = make_float4(o[v4 * 4 + 0] * inv, o[v4 * 4 + 1] * inv,
                                o[v4 * 4 + 2] * inv, o[v4 * 4 + 3] * inv);
        *(float4*)(outp + v4 * 4) = ov;
    }
}

// ---------------------------------------------------------------------------
// kernel_launch: x, mask, wq, wk, wv, wo -> out (B,T,E) fp32
// ---------------------------------------------------------------------------
extern "C" void kernel_launch(void* const* d_in, const int* in_sizes, int n_in,
                              void* d_out, int out_size)
{
    const float* x  = (const float*)d_in[0];
    // d_in[1] = causal mask (unused: causality computed directly)
    const float* wq = (const float*)d_in[2];
    const float* wk = (const float*)d_in[3];
    const float* wv = (const float*)d_in[4];
    const float* wo = (const float*)d_in[5];
    float* out = (float*)d_out;

    float *Qp, *Kp, *Vp, *AOp, *WTp;
    cudaGetSymbolAddress((void**)&Qp,  g_Q);
    cudaGetSymbolAddress((void**)&Kp,  g_K);
    cudaGetSymbolAddress((void**)&Vp,  g_V);
    cudaGetSymbolAddress((void**)&AOp, g_AO);
    cudaGetSymbolAddress((void**)&WTp, g_WT);

    cudaFuncSetAttribute(gemm_mma, cudaFuncAttributeMaxDynamicSharedMemorySize, GEMM_SMEM);

    // Q = X @ Wq
    {
        dim3 tg(E_DIM / 32, E_DIM / 32);
        transpose_round_kernel<<<tg, dim3(32, 8)>>>(wq, WTp, E_DIM, QW);
        dim3 grid(QW / 128, ROWS / 128);
        gemm_mma<<<grid, 256, GEMM_SMEM>>>(x, WTp, Qp, ROWS, QW, E_DIM);
    }
    // K = X @ Wk
    {
        dim3 tg(KW / 32, E_DIM / 32);
        transpose_round_kernel<<<tg, dim3(32, 8)>>>(wk, WTp, E_DIM, KW);
        dim3 grid(KW / 128, ROWS / 128);
        gemm_mma<<<grid, 256, GEMM_SMEM>>>(x, WTp, Kp, ROWS, KW, E_DIM);
    }
    // V = X @ Wv
    {
        dim3 tg(KW / 32, E_DIM / 32);
        transpose_round_kernel<<<tg, dim3(32, 8)>>>(wv, WTp, E_DIM, KW);
        dim3 grid(KW / 128, ROWS / 128);
        gemm_mma<<<grid, 256, GEMM_SMEM>>>(x, WTp, Vp, ROWS, KW, E_DIM);
    }

    // RoPE
    {
        int n = T_SEQ * (HD / 2);
        rope_table_kernel<<<(n + 255) / 256, 256>>>();
        int nq = ROWS * NH * (HD / 2);
        rope_apply_kernel<<<(nq + 255) / 256, 256>>>(Qp, NH);
        int nk = ROWS * NKV * (HD / 2);
        rope_apply_kernel<<<(nk + 255) / 256, 256>>>(Kp, NKV);
    }

    // Attention
    {
        dim3 grid(T_SEQ / 32, B_SZ * NH);
        attn_kernel<<<grid, 256>>>();
    }

    // out = AO @ Wo
    {
        dim3 tg(E_DIM / 32, QW / 32);
        transpose_round_kernel<<<tg, dim3(32, 8)>>>(wo, WTp, QW, E_DIM);
        dim3 grid(E_DIM / 128, ROWS / 128);
        gemm_mma<<<grid, 256, GEMM_SMEM>>>(AOp, WTp, out, ROWS, E_DIM, E_DIM);
    }
}

// round 16
// speedup vs baseline: 7.7086x; 7.6242x over previous
#include <cuda_runtime.h>
#include <math.h>
#include <stdint.h>

// Problem constants
#define B_SZ   2
#define T_SEQ  2048
#define E_DIM  2048
#define NH     16
#define NKV    8
#define HD     128
#define ROWS   (B_SZ * T_SEQ)        // 4096
#define QW     (NH * HD)             // 2048
#define KW     (NKV * HD)            // 1024

// Scratch (static device globals; no dynamic allocation allowed)
__device__ float g_Q[(size_t)ROWS * QW];       // 32 MB
__device__ float g_K[(size_t)ROWS * KW];       // 16 MB
__device__ float g_V[(size_t)ROWS * KW];       // 16 MB
__device__ float g_AO[(size_t)ROWS * QW];      // 32 MB
__device__ float g_WT[(size_t)QW * E_DIM + 2 * (size_t)KW * E_DIM + (size_t)E_DIM * QW]; // 48 MB
__device__ float g_cos[T_SEQ * (HD / 2)];
__device__ float g_sin[T_SEQ * (HD / 2)];

#define WT_Q ((size_t)0)
#define WT_K ((size_t)QW * E_DIM)
#define WT_V ((size_t)QW * E_DIM + (size_t)KW * E_DIM)
#define WT_O ((size_t)QW * E_DIM + 2 * (size_t)KW * E_DIM)

// ---------------------------------------------------------------------------
// Helpers
// ---------------------------------------------------------------------------
__device__ __forceinline__ float to_tf32(float x) {
    uint32_t u;
    asm("cvt.rna.tf32.f32 %0, %1;" : "=r"(u) : "f"(x));
    return __uint_as_float(u);
}

__device__ __forceinline__ void mma_tf32(float* d, const uint32_t* a, const uint32_t* b) {
    asm volatile(
        "mma.sync.aligned.m16n8k8.row.col.f32.tf32.tf32.f32 "
        "{%0,%1,%2,%3}, {%4,%5,%6,%7}, {%8,%9}, {%0,%1,%2,%3};\n"
        : "+f"(d[0]), "+f"(d[1]), "+f"(d[2]), "+f"(d[3])
        : "r"(a[0]), "r"(a[1]), "r"(a[2]), "r"(a[3]), "r"(b[0]), "r"(b[1]));
}

// ---------------------------------------------------------------------------
// TF32 mma.sync GEMM (proven R7): C[M,N] = A[M,K] @ Bt[N,K]^T.
// rope!=0: apply RoPE to output (even,odd) column pairs in the epilogue.
// ---------------------------------------------------------------------------
#define GBK 32
#define STG_BYTES 32768
#define GEMM_SMEM (2 * STG_BYTES)

__global__ __launch_bounds__(256) void gemm_mma(
    const float* __restrict__ A, const float* __restrict__ Bt,
    float* __restrict__ C, int M, int N, int K, int rope)
{
    extern __shared__ char smc[];
    const int tid = threadIdx.x;
    const int lane = tid & 31, warp = tid >> 5;
    const int lq = lane >> 2, s4 = lane & 3;
    const int wm = warp >> 2, wn = warp & 3;
    const int m0 = blockIdx.y * 128, n0 = blockIdx.x * 128;

    const int sk8 = tid & 3;
    const int slq = (tid >> 2) & 7;
    const int sgrp = tid >> 5;

    const float* Ag0 = A + (size_t)(m0 + sgrp * 16 + slq) * K + sk8 * 8;
    const float* Ag1 = Ag0 + (size_t)8 * K;
    const float* Bg0 = Bt + (size_t)(n0 + sgrp * 16 + slq) * K + sk8 * 8;
    const float* Bg1 = Bg0 + (size_t)8 * K;

    const int sts_base = (sk8 * 8 + sgrp) * 32;

    float ar0[8], ar1[8], br0[8], br1[8];

    auto LDGALL = [&](int kt) {
        const float* a0 = Ag0 + kt * GBK;
        const float* a1 = Ag1 + kt * GBK;
        const float* b0 = Bg0 + kt * GBK;
        const float* b1 = Bg1 + kt * GBK;
        *(float4*)(ar0)     = *(const float4*)(a0);
        *(float4*)(ar0 + 4) = *(const float4*)(a0 + 4);
        *(float4*)(ar1)     = *(const float4*)(a1);
        *(float4*)(ar1 + 4) = *(const float4*)(a1 + 4);
        *(float4*)(br0)     = *(const float4*)(b0);
        *(float4*)(br0 + 4) = *(const float4*)(b0 + 4);
        *(float4*)(br1)     = *(const float4*)(b1);
        *(float4*)(br1 + 4) = *(const float4*)(b1 + 4);
    };
    auto STSALL = [&](int st) {
        float4* As = (float4*)(smc + st * STG_BYTES);
        float4* Bs = (float4*)(smc + st * STG_BYTES + 16384);
#pragma unroll
        for (int j = 0; j < 4; j++) {
            const int slot = slq * 4 + (j ^ sk8);
            As[sts_base + slot] = make_float4(to_tf32(ar0[j]), to_tf32(ar1[j]),
                                              to_tf32(ar0[j + 4]), to_tf32(ar1[j + 4]));
            Bs[sts_base + slot] = make_float4(br0[j], br1[j], br0[j + 4], br1[j + 4]);
        }
    };

    float acc[4][4][4];
#pragma unroll
    for (int mi = 0; mi < 4; mi++)
#pragma unroll
        for (int ni = 0; ni < 4; ni++)
#pragma unroll
            for (int j = 0; j < 4; j++) acc[mi][ni][j] = 0.f;

    const int nk = K / GBK;

    LDGALL(0);
    STSALL(0);
    __syncthreads();

    for (int kt = 0; kt < nk; kt++) {
        if (kt + 1 < nk) LDGALL(kt + 1);

        const float4* As = (const float4*)(smc + (kt & 1) * STG_BYTES);
        const float4* Bs = (const float4*)(smc + (kt & 1) * STG_BYTES + 16384);

#pragma unroll
        for (int k8 = 0; k8 < 4; k8++) {
            const int cslot = lq * 4 + (s4 ^ k8);
            uint32_t af[4][4], bf[4][2];
#pragma unroll
            for (int mi = 0; mi < 4; mi++) {
                float4 q = As[(k8 * 8 + wm * 4 + mi) * 32 + cslot];
                af[mi][0] = __float_as_uint(q.x); af[mi][1] = __float_as_uint(q.y);
                af[mi][2] = __float_as_uint(q.z); af[mi][3] = __float_as_uint(q.w);
            }
#pragma unroll
            for (int g = 0; g < 2; g++) {
                float4 q = Bs[(k8 * 8 + wn * 2 + g) * 32 + cslot];
                bf[g * 2 + 0][0] = __float_as_uint(q.x); bf[g * 2 + 0][1] = __float_as_uint(q.z);
                bf[g * 2 + 1][0] = __float_as_uint(q.y); bf[g * 2 + 1][1] = __float_as_uint(q.w);
            }
#pragma unroll
            for (int mi = 0; mi < 4; mi++)
#pragma unroll
                for (int ni = 0; ni < 4; ni++)
                    mma_tf32(acc[mi][ni], af[mi], bf[ni]);
        }

        if (kt + 1 < nk) {
            STSALL((kt + 1) & 1);
            __syncthreads();
        }
    }

    // Epilogue (optional fused RoPE on (even,odd) output column pairs)
#pragma unroll
    for (int mi = 0; mi < 4; mi++) {
        const int r0 = m0 + wm * 64 + mi * 16 + lq;
#pragma unroll
        for (int ni = 0; ni < 4; ni++) {
            const int c = n0 + wn * 32 + ni * 8 + s4 * 2;
            float x0 = acc[mi][ni][0], x1 = acc[mi][ni][1];
            float y0 = acc[mi][ni][2], y1 = acc[mi][ni][3];
            if (rope) {
                const int i = (c & 127) >> 1;
                const int tA = r0 & (T_SEQ - 1);
                const int tB = (r0 + 8) & (T_SEQ - 1);
                float ca = g_cos[tA * 64 + i], sa = g_sin[tA * 64 + i];
                float cb = g_cos[tB * 64 + i], sb = g_sin[tB * 64 + i];
                float t0 = x0 * ca - x1 * sa, t1 = x0 * sa + x1 * ca;
                float u0 = y0 * cb - y1 * sb, u1 = y0 * sb + y1 * cb;
                x0 = t0; x1 = t1; y0 = u0; y1 = u1;
            }
            *(float2*)(C + (size_t)r0 * N + c)       = make_float2(x0, x1);
            *(float2*)(C + (size_t)(r0 + 8) * N + c) = make_float2(y0, y1);
        }
    }
}

// ---------------------------------------------------------------------------
// RoPE table: cos/sin in double precision
// ---------------------------------------------------------------------------
__global__ void rope_table_kernel()
{
    int idx = blockIdx.x * blockDim.x + threadIdx.x;
    if (idx >= T_SEQ * (HD / 2)) return;
    int t = idx / (HD / 2);
    int i = idx % (HD / 2);
    double inv = pow(10000.0, -(double)(2 * i) / (double)HD);
    double ang = (double)t * inv;
    double s, c;
    sincos(ang, &s, &c);
    g_cos[idx] = (float)c;
    g_sin[idx] = (float)s;
}

// ---------------------------------------------------------------------------
// Fused transpose + tf32 rounding for all 4 weights (single launch).
// out[C][R] = rna_tf32(in[R][C])^T per z-slice.
// ---------------------------------------------------------------------------
__global__ void transpose_all_kernel(const float* __restrict__ wq, const float* __restrict__ wk,
                                     const float* __restrict__ wv, const float* __restrict__ wo)
{
    __shared__ float t[32][33];
    const int z = blockIdx.z;
    const float* src;
    float* dst;
    int R = E_DIM, C;
    if (z == 0)      { src = wq; C = QW;    dst = g_WT + WT_Q; }
    else if (z == 1) { src = wk; C = KW;    dst = g_WT + WT_K; }
    else if (z == 2) { src = wv; C = KW;    dst = g_WT + WT_V; }
    else             { src = wo; C = E_DIM; dst = g_WT + WT_O; R = QW; }

    const int bx = blockIdx.x * 32, by = blockIdx.y * 32;
    if (bx >= C || by >= R) return;
    const int tx = threadIdx.x, ty = threadIdx.y;
#pragma unroll
    for (int i = 0; i < 32; i += 8)
        t[ty + i][tx] = to_tf32(src[(size_t)(by + ty + i) * C + bx + tx]);
    __syncthreads();
#pragma unroll
    for (int i = 0; i < 32; i += 8)
        dst[(size_t)(bx + ty + i) * R + by + tx] = t[tx][ty + i];
}

// ---------------------------------------------------------------------------
// Tensor-core flash attention (tf32 mma, causal, GQA 2:1).
// Block: 64 q-rows for one (b,h); 256 threads = 8 warps = 4 row-groups x 2 halves.
// Per 64-key tile: S = Q@K^T (warp: 16 rows x 32-key half) -> online softmax
// (cross-half combine via smem) -> P (row pitch 68, aliases K buffer) @ V
// (warp: 16 rows x 64-dim half).
// ---------------------------------------------------------------------------
#define SQ_OFF  0          // Q quad fragments: 8192 floats
#define SK_OFF  8192       // K tile 64x128 (P 64x68 aliases it)
#define SV_OFF  16384      // V tile 64x128
#define SST_OFF 24576      // hmax[2][64], hsum[2][64]
#define ATT_SMEM ((24576 + 256) * 4)   // 99328 bytes
#define P_LD 68

__global__ __launch_bounds__(256, 2) void attn_mma()
{
    extern __shared__ float sm[];
    const int tid = threadIdx.x;
    const int lane = tid & 31, warp = tid >> 5;
    const int lq = lane >> 2, s4 = lane & 3;
    const int wr = warp >> 1, wh = warp & 1;

    const int qb = blockIdx.x;
    const int bh = blockIdx.y;
    const int b = bh >> 4, h = bh & 15, kh = h >> 1;
    const int r0 = qb * 64;

    const float scale = 0.08838834764831845f;  // 128^-0.5

    // Stage Q as quad fragments: quad id = kb*128 + wrq*32 + lqq*4 + s4q holds
    // {Q[wrq*16+lqq][kb*8+s4q], Q[+8][..], Q[..][+4], Q[+8][+4]} * scale, tf32.
    {
        const float* Qg = g_Q + ((size_t)(b * T_SEQ + r0)) * QW + h * HD;
#pragma unroll
        for (int j = 0; j < 8; j++) {
            int id = tid + j * 256;
            int s4q = id & 3, lqq = (id >> 2) & 7, wrq = (id >> 5) & 3, kbq = id >> 7;
            int rA = wrq * 16 + lqq, rB = rA + 8;
            int c0 = kbq * 8 + s4q, c1 = c0 + 4;
            float4 v;
            v.x = to_tf32(Qg[(size_t)rA * QW + c0] * scale);
            v.y = to_tf32(Qg[(size_t)rB * QW + c0] * scale);
            v.z = to_tf32(Qg[(size_t)rA * QW + c1] * scale);
            v.w = to_tf32(Qg[(size_t)rB * QW + c1] * scale);
            ((float4*)(sm + SQ_OFF))[id] = v;
        }
    }

    const int rlo = wr * 16 + lq, rhi = rlo + 8;

    float m_lo = -INFINITY, m_hi = -INFINITY, l_lo = 0.f, l_hi = 0.f;
    float oa[8][4];
#pragma unroll
    for (int nf = 0; nf < 8; nf++)
#pragma unroll
        for (int j = 0; j < 4; j++) oa[nf][j] = 0.f;

    for (int t = 0; t <= qb; t++) {
        const int k0 = t * 64;
        __syncthreads();  // prior PV reads done; Q staging visible (t=0)

        // Stage K (^((r&7)<<2)) and V (^((r&3)<<3)), rna-tf32, coalesced.
        {
            const float* Kg = g_K + ((size_t)(b * T_SEQ + k0)) * KW + kh * HD;
            const float* Vg = g_V + ((size_t)(b * T_SEQ + k0)) * KW + kh * HD;
#pragma unroll
            for (int i = 0; i < 8; i++) {
                int r = warp * 8 + i;
                float4 kv = *(const float4*)(Kg + (size_t)r * KW + 4 * lane);
                kv.x = to_tf32(kv.x); kv.y = to_tf32(kv.y);
                kv.z = to_tf32(kv.z); kv.w = to_tf32(kv.w);
                *(float4*)(sm + SK_OFF + r * 128 + ((4 * lane) ^ ((r & 7) << 2))) = kv;
                float4 vv = *(const float4*)(Vg + (size_t)r * KW + 4 * lane);
                vv.x = to_tf32(vv.x); vv.y = to_tf32(vv.y);
                vv.z = to_tf32(vv.z); vv.w = to_tf32(vv.w);
                *(float4*)(sm + SV_OFF + r * 128 + ((4 * lane) ^ ((r & 3) << 3))) = vv;
            }
        }
        __syncthreads();  // tiles staged

        // ---- S = Q @ K^T : warp computes 16 rows x 32 keys (half wh) ----
        float sa[4][4];
#pragma unroll
        for (int nf = 0; nf < 4; nf++)
#pragma unroll
            for (int j = 0; j < 4; j++) sa[nf][j] = 0.f;

#pragma unroll
        for (int kb = 0; kb < 16; kb++) {
            float4 qa = ((const float4*)(sm + SQ_OFF))[(kb * 4 + wr) * 32 + lane];
            uint32_t af[4] = {__float_as_uint(qa.x), __float_as_uint(qa.y),
                              __float_as_uint(qa.z), __float_as_uint(qa.w)};
#pragma unroll
            for (int nf = 0; nf < 4; nf++) {
                const int n = wh * 32 + nf * 8 + lq;
                const int sw = (n & 7) << 2;
                uint32_t bf[2];
                bf[0] = __float_as_uint(sm[SK_OFF + n * 128 + ((kb * 8 + s4) ^ sw)]);
                bf[1] = __float_as_uint(sm[SK_OFF + n * 128 + ((kb * 8 + s4 + 4) ^ sw)]);
                mma_tf32(sa[nf], af, bf);
            }
        }

        // Causal mask on diagonal tile
        if (t == qb) {
            const int rg_lo = r0 + rlo, rg_hi = r0 + rhi;
#pragma unroll
            for (int nf = 0; nf < 4; nf++) {
                const int kg = k0 + wh * 32 + nf * 8 + 2 * s4;
                if (kg     > rg_lo) sa[nf][0] = -1e30f;
                if (kg + 1 > rg_lo) sa[nf][1] = -1e30f;
                if (kg     > rg_hi) sa[nf][2] = -1e30f;
                if (kg + 1 > rg_hi) sa[nf][3] = -1e30f;
            }
        }

        // Row max within half, reduce over s4, publish to smem
        float mx0 = fmaxf(fmaxf(sa[0][0], sa[0][1]), fmaxf(sa[1][0], sa[1][1]));
        mx0 = fmaxf(mx0, fmaxf(fmaxf(sa[2][0], sa[2][1]), fmaxf(sa[3][0], sa[3][1])));
        float mx1 = fmaxf(fmaxf(sa[0][2], sa[0][3]), fmaxf(sa[1][2], sa[1][3]));
        mx1 = fmaxf(mx1, fmaxf(fmaxf(sa[2][2], sa[2][3]), fmaxf(sa[3][2], sa[3][3])));
        mx0 = fmaxf(mx0, __shfl_xor_sync(0xffffffffu, mx0, 1));
        mx0 = fmaxf(mx0, __shfl_xor_sync(0xffffffffu, mx0, 2));
        mx1 = fmaxf(mx1, __shfl_xor_sync(0xffffffffu, mx1, 1));
        mx1 = fmaxf(mx1, __shfl_xor_sync(0xffffffffu, mx1, 2));
        if (s4 == 0) {
            sm[SST_OFF + wh * 64 + rlo] = mx0;
            sm[SST_OFF + wh * 64 + rhi] = mx1;
        }
        __syncthreads();  // half-maxes ready; all S reads of K done -> P may alias

        const float mn_lo = fmaxf(m_lo, fmaxf(sm[SST_OFF + rlo], sm[SST_OFF + 64 + rlo]));
        const float mn_hi = fmaxf(m_hi, fmaxf(sm[SST_OFF + rhi], sm[SST_OFF + 64 + rhi]));
        const float corr_lo = __expf(m_lo - mn_lo);
        const float corr_hi = __expf(m_hi - mn_hi);
        m_lo = mn_lo; m_hi = mn_hi;

        // P = exp(S - m) -> P buffer (pitch 68), accumulate half-sums
        float sum0 = 0.f, sum1 = 0.f;
#pragma unroll
        for (int nf = 0; nf < 4; nf++) {
            float p0 = __expf(sa[nf][0] - mn_lo), p1 = __expf(sa[nf][1] - mn_lo);
            float p2 = __expf(sa[nf][2] - mn_hi), p3 = __expf(sa[nf][3] - mn_hi);
            sum0 += p0 + p1; sum1 += p2 + p3;
            const int c = wh * 32 + nf * 8 + 2 * s4;
            *(float2*)(sm + SK_OFF + rlo * P_LD + c) = make_float2(to_tf32(p0), to_tf32(p1));
            *(float2*)(sm + SK_OFF + rhi * P_LD + c) = make_float2(to_tf32(p2), to_tf32(p3));
        }
        sum0 += __shfl_xor_sync(0xffffffffu, sum0, 1);
        sum0 += __shfl_xor_sync(0xffffffffu, sum0, 2);
        sum1 += __shfl_xor_sync(0xffffffffu, sum1, 1);
        sum1 += __shfl_xor_sync(0xffffffffu, sum1, 2);
        if (s4 == 0) {
            sm[SST_OFF + 128 + wh * 64 + rlo] = sum0;
            sm[SST_OFF + 128 + wh * 64 + rhi] = sum1;
        }
        __syncthreads();  // P + half-sums visible

        l_lo = l_lo * corr_lo + sm[SST_OFF + 128 + rlo] + sm[SST_OFF + 192 + rlo];
        l_hi = l_hi * corr_hi + sm[SST_OFF + 128 + rhi] + sm[SST_OFF + 192 + rhi];
#pragma unroll
        for (int nf = 0; nf < 8; nf++) {
            oa[nf][0] *= corr_lo; oa[nf][1] *= corr_lo;
            oa[nf][2] *= corr_hi; oa[nf][3] *= corr_hi;
        }

        // ---- PV: warp computes 16 rows x 64 dims (half wh) ----
#pragma unroll
        for (int kb = 0; kb < 8; kb++) {
            uint32_t af[4];
            af[0] = __float_as_uint(sm[SK_OFF + rlo * P_LD + kb * 8 + s4]);
            af[1] = __float_as_uint(sm[SK_OFF + rhi * P_LD + kb * 8 + s4]);
            af[2] = __float_as_uint(sm[SK_OFF + rlo * P_LD + kb * 8 + s4 + 4]);
            af[3] = __float_as_uint(sm[SK_OFF + rhi * P_LD + kb * 8 + s4 + 4]);
            const int k = kb * 8 + s4;
            const int swv = s4 << 3;
#pragma unroll
            for (int nf = 0; nf < 8; nf++) {
                const int n = wh * 64 + nf * 8 + lq;
                uint32_t bf[2];
                bf[0] = __float_as_uint(sm[SV_OFF + k * 128 + (n ^ swv)]);
                bf[1] = __float_as_uint(sm[SV_OFF + (k + 4) * 128 + (n ^ swv)]);
                mma_tf32(oa[nf], af, bf);
            }
        }
    }

    // Normalize and write
    const float inv_lo = 1.f / l_lo, inv_hi = 1.f / l_hi;
    float* Og = g_AO + ((size_t)(b * T_SEQ + r0 + wr * 16)) * QW + h * HD;
#pragma unroll
    for (int nf = 0; nf < 8; nf++) {
        const int c = wh * 64 + nf * 8 + 2 * s4;
        *(float2*)(Og + (size_t)lq * QW + c) =
            make_float2(oa[nf][0] * inv_lo, oa[nf][1] * inv_lo);
        *(float2*)(Og + (size_t)(lq + 8) * QW + c) =
            make_float2(oa[nf][2] * inv_hi, oa[nf][3] * inv_hi);
    }
}

// ---------------------------------------------------------------------------
// kernel_launch: x, mask, wq, wk, wv, wo -> out (B,T,E) fp32
// Launch order: 0 rope_table, 1 transposeAll, 2 gemmQ, 3 gemmK, 4 gemmV,
//               5 attn (ncu -s 5 profiles this), 6 gemmO.
// ---------------------------------------------------------------------------
extern "C" void kernel_launch(void* const* d_in, const int* in_sizes, int n_in,
                              void* d_out, int out_size)
{
    const float* x  = (const float*)d_in[0];
    // d_in[1] = causal mask (unused: causality computed directly)
    const float* wq = (const float*)d_in[2];
    const float* wk = (const float*)d_in[3];
    const float* wv = (const float*)d_in[4];
    const float* wo = (const float*)d_in[5];
    float* out = (float*)d_out;

    float *Qp, *Kp, *Vp, *AOp, *WTp;
    cudaGetSymbolAddress((void**)&Qp,  g_Q);
    cudaGetSymbolAddress((void**)&Kp,  g_K);
    cudaGetSymbolAddress((void**)&Vp,  g_V);
    cudaGetSymbolAddress((void**)&AOp, g_AO);
    cudaGetSymbolAddress((void**)&WTp, g_WT);

    cudaFuncSetAttribute(gemm_mma, cudaFuncAttributeMaxDynamicSharedMemorySize, GEMM_SMEM);
    cudaFuncSetAttribute(attn_mma, cudaFuncAttributeMaxDynamicSharedMemorySize, ATT_SMEM);

    // 0: RoPE table
    {
        int n = T_SEQ * (HD / 2);
        rope_table_kernel<<<(n + 255) / 256, 256>>>();
    }
    // 1: all weight transposes (tf32-rounded)
    {
        dim3 grid(E_DIM / 32, E_DIM / 32, 4);
        transpose_all_kernel<<<grid, dim3(32, 8)>>>(wq, wk, wv, wo);
    }
    // 2: Q = X @ Wq (+RoPE)
    {
        dim3 grid(QW / 128, ROWS / 128);
        gemm_mma<<<grid, 256, GEMM_SMEM>>>(x, WTp + WT_Q, Qp, ROWS, QW, E_DIM, 1);
    }
    // 3: K = X @ Wk (+RoPE)
    {
        dim3 grid(KW / 128, ROWS / 128);
        gemm_mma<<<grid, 256, GEMM_SMEM>>>(x, WTp + WT_K, Kp, ROWS, KW, E_DIM, 1);
    }
    // 4: V = X @ Wv
    {
        dim3 grid(KW / 128, ROWS / 128);
        gemm_mma<<<grid, 256, GEMM_SMEM>>>(x, WTp + WT_V, Vp, ROWS, KW, E_DIM, 0);
    }
    // 5: attention (tensor-core flash)
    {
        dim3 grid(T_SEQ / 64, B_SZ * NH);
        attn_mma<<<grid, 256, ATT_SMEM>>>();
    }
    // 6: out = AO @ Wo
    {
        dim3 grid(E_DIM / 128, ROWS / 128);
        gemm_mma<<<grid, 256, GEMM_SMEM>>>(AOp, WTp + WT_O, out, ROWS, E_DIM, E_DIM, 0);
    }
}